// round 12
// baseline (speedup 1.0000x reference)
#include <cuda_runtime.h>
#include <cuda_bf16.h>
#include <cstdint>
#include <math.h>

#define N_ROWS 8192
#define H_DIM  1024
#define NTILE  32                    // N_ROWS / 256 column tiles
#define INV_T  (1.0f/0.07f)
#define EX2_SCALE 20.609929f         // INV_T * log2(e)

// GEMM tiling: CTA 128(M) x 256(N), BK=64, 3 stages, 16 warps of 32x64, 1 CTA/SM
#define TM 128
#define TN 256
#define KC 64
#define KT_STEPS (H_DIM / KC)        // 16
#define ST 3
#define NT 512
#define A_BYTES (TM * 128)           // 16 KB
#define B_BYTES (TN * 128)           // 32 KB
#define STAGE_BYTES (A_BYTES + B_BYTES)      // 48 KB
#define SMEM_DYN (1024 + ST * STAGE_BYTES)   // 148,480 B

// ---------------- scratch (device globals; no runtime allocation) ----------
__device__ __nv_bfloat16 g_A[(size_t)N_ROWS * H_DIM];
__device__ __nv_bfloat16 g_B[(size_t)N_ROWS * H_DIM];
__device__ float g_pmax[(size_t)N_ROWS * NTILE];
__device__ int   g_pidx[(size_t)N_ROWS * NTILE];
__device__ float g_psum[(size_t)N_ROWS * NTILE];   // relative to g_pmax
__device__ float g_logl[N_ROWS];
__device__ int   g_pos[N_ROWS];
__device__ float g_nn[N_ROWS];

// ---------------- helpers ---------------------------------------------------
__device__ __forceinline__ void cp16s(uint32_t s, const void* g) {
    asm volatile("cp.async.cg.shared.global [%0], [%1], 16;" :: "r"(s), "l"(g));
}
__device__ __forceinline__ float fex2(float x) {
    float y; asm("ex2.approx.f32 %0, %1;" : "=f"(y) : "f"(x)); return y;
}
// exp(x) on FMA pipe for the merge kernel (x <= 0)
__device__ __forceinline__ float fexp(float x) {
    float t = x * 1.4426950408889634f;
    float fl = floorf(t);
    float f = t - fl;
    float p = 1.5403530e-4f;
    p = fmaf(p, f, 1.3333558e-3f);
    p = fmaf(p, f, 9.6181291e-3f);
    p = fmaf(p, f, 5.5504110e-2f);
    p = fmaf(p, f, 2.4022651e-1f);
    p = fmaf(p, f, 6.9314718e-1f);
    p = fmaf(p, f, 1.0f);
    return __int_as_float((uint32_t)((int)fl + 127) << 23) * p;
}
__device__ __forceinline__ uint32_t sw128(uint32_t off) {   // Swizzle<3,4,3>
    return off ^ ((off >> 3) & 0x70);
}
#define LDSM4(r0, r1, r2, r3, addr)                                            \
    asm volatile("ldmatrix.sync.aligned.m8n8.x4.shared.b16 {%0,%1,%2,%3}, [%4];" \
                 : "=r"(r0), "=r"(r1), "=r"(r2), "=r"(r3) : "r"(addr))
#define HMMA(acc, a, b)                                                        \
    asm volatile("mma.sync.aligned.m16n8k16.row.col.f32.bf16.bf16.f32 "        \
                 "{%0,%1,%2,%3},{%4,%5,%6,%7},{%8,%9},{%0,%1,%2,%3};"          \
                 : "+f"((acc)[0]), "+f"((acc)[1]), "+f"((acc)[2]), "+f"((acc)[3]) \
                 : "r"((a)[0]), "r"((a)[1]), "r"((a)[2]), "r"((a)[3]),         \
                   "r"((b)[0]), "r"((b)[1]))

// ---------------- kernel 1: row L2-normalize -> bf16 -----------------------
__global__ __launch_bounds__(256) void norm_kernel(const float* __restrict__ src,
                                                   const float* __restrict__ tgt) {
    int row = blockIdx.x;
    const float* in;
    __nv_bfloat16* out;
    if (row < N_ROWS) { in = src + (size_t)row * H_DIM;            out = g_A + (size_t)row * H_DIM; }
    else              { in = tgt + (size_t)(row - N_ROWS) * H_DIM; out = g_B + (size_t)(row - N_ROWS) * H_DIM; }

    int t = threadIdx.x;                          // cols 4t..4t+3
    float4 v = ((const float4*)in)[t];
    float ss = v.x * v.x + v.y * v.y + v.z * v.z + v.w * v.w;
#pragma unroll
    for (int o = 16; o; o >>= 1) ss += __shfl_xor_sync(0xffffffffu, ss, o);
    __shared__ float red[8];
    if ((t & 31) == 0) red[t >> 5] = ss;
    __syncthreads();
    float total = red[0] + red[1] + red[2] + red[3] + red[4] + red[5] + red[6] + red[7];
    float sc = 1.0f / fmaxf(sqrtf(total), 1e-12f);

    __nv_bfloat162 p0; p0.x = __float2bfloat16(v.x * sc); p0.y = __float2bfloat16(v.y * sc);
    __nv_bfloat162 p1; p1.x = __float2bfloat16(v.z * sc); p1.y = __float2bfloat16(v.w * sc);
    ((__nv_bfloat162*)out)[2 * t]     = p0;
    ((__nv_bfloat162*)out)[2 * t + 1] = p1;
}

// ---------------- kernel 2: HMMA GEMM (128x256, 512 thr) + fused softmax ----
// 16 warps as 4(M) x 4(N), warp tile 32x64; 1 CTA/SM, 16 warps coverage.
__global__ __launch_bounds__(NT, 1) void gemm_fused_kernel() {
    extern __shared__ __align__(16) char dsm[];
    uint32_t raw  = (uint32_t)__cvta_generic_to_shared(dsm);
    uint32_t base = (raw + 1023u) & ~1023u;

    const int tid   = threadIdx.x;
    const int lane  = tid & 31;
    const int warp  = tid >> 5;
    const int warpM = warp & 3;             // 0..3 -> rows warpM*32
    const int warpN = warp >> 2;            // 0..3 -> cols warpN*64
    const int wm = warpM * 32;
    const int wn = warpN * 64;
    const int brow = blockIdx.y * TM;
    const int bcol = blockIdx.x * TN;

    float acc[2][8][4];
#pragma unroll
    for (int im = 0; im < 2; im++)
#pragma unroll
        for (int in = 0; in < 8; in++)
#pragma unroll
            for (int k = 0; k < 4; k++) acc[im][in][k] = 0.f;

    // swizzled ldmatrix bases; k-slice step kb hits bits 5-6 only:
    // sw128(o + kb) == sw128(o) ^ kb   (XOR — swizzle may set bits 5-6)
    uint32_t aoff[2], boff[4];
#pragma unroll
    for (int im = 0; im < 2; im++)
        aoff[im] = sw128((uint32_t)((wm + im * 16 + (lane & 15)) * 128 + ((lane >> 4) << 4)));
#pragma unroll
    for (int ib = 0; ib < 4; ib++)
        boff[ib] = sw128((uint32_t)((wn + ib * 16 + ((lane >> 4) << 3) + (lane & 7)) * 128
                                    + (((lane >> 3) & 1) << 4)));

    auto load_stage = [&](int s, int kt) {
        const char* gA = (const char*)g_A + (size_t)brow * (H_DIM * 2) + kt * (KC * 2);
        const char* gB = (const char*)g_B + (size_t)bcol * (H_DIM * 2) + kt * (KC * 2);
        uint32_t aB = base + s * STAGE_BYTES;
        uint32_t bB = aB + A_BYTES;
#pragma unroll
        for (int i = tid; i < TM * 8; i += NT) {        // 2 per thread
            int r = i >> 3, c = i & 7;
            cp16s(aB + sw128((uint32_t)(r * 128 + c * 16)), gA + (size_t)r * (H_DIM * 2) + c * 16);
        }
#pragma unroll
        for (int i = tid; i < TN * 8; i += NT) {        // 4 per thread
            int r = i >> 3, c = i & 7;
            cp16s(bB + sw128((uint32_t)(r * 128 + c * 16)), gB + (size_t)r * (H_DIM * 2) + c * 16);
        }
    };

    // prefill ST-1 stages
#pragma unroll
    for (int p = 0; p < ST - 1; p++) {
        load_stage(p, p);
        asm volatile("cp.async.commit_group;");
    }

    int s = 0, sNext = ST - 1;                 // single barrier per kt (R11-proven)
    for (int kt = 0; kt < KT_STEPS; kt++) {
        asm volatile("cp.async.wait_group %0;" :: "n"(ST - 2));
        __syncthreads();    // stage s ready AND all warps done reading stage sNext

        if (kt + ST - 1 < KT_STEPS) load_stage(sNext, kt + ST - 1);
        asm volatile("cp.async.commit_group;"); // uniform group accounting

        uint32_t aT = base + s * STAGE_BYTES;
        uint32_t bT = aT + A_BYTES;
#pragma unroll
        for (int ks = 0; ks < 4; ks++) {            // 4 x k16 slices
            uint32_t kb = (uint32_t)(ks * 32);
            uint32_t a[2][4], b[4][4];
#pragma unroll
            for (int im = 0; im < 2; im++)
                LDSM4(a[im][0], a[im][1], a[im][2], a[im][3], aT + (aoff[im] ^ kb));
#pragma unroll
            for (int ib = 0; ib < 4; ib++)
                LDSM4(b[ib][0], b[ib][1], b[ib][2], b[ib][3], bT + (boff[ib] ^ kb));
#pragma unroll
            for (int im = 0; im < 2; im++)
#pragma unroll
                for (int ib = 0; ib < 4; ib++) {
                    HMMA(acc[im][2 * ib],     a[im], &b[ib][0]);
                    HMMA(acc[im][2 * ib + 1], a[im], &b[ib][2]);
                }
        }
        sNext = s;
        s = (s + 1 < ST) ? s + 1 : 0;
    }
    __syncthreads();        // all warps done with final stage before SMEM reuse

    // ---- epilogue: reuse stage SMEM for per-row partials (R5-proven 4-col) --
    float* s_max = (float*)(dsm + (base - raw));          // [128][4]
    int*   s_idx = (int*)  (s_max + 128 * 4);
    float* s_sum = (float*)(s_idx + 128 * 4);

    // phase 1: per-warp (max, argmax) over its 64 cols
#pragma unroll
    for (int im = 0; im < 2; im++)
#pragma unroll
        for (int half = 0; half < 2; half++) {
            float m = -3.402823e38f; int id = 0;
#pragma unroll
            for (int in = 0; in < 8; in++)
#pragma unroll
                for (int j = 0; j < 2; j++) {
                    float v = acc[im][in][half * 2 + j];
                    int c = bcol + wn + in * 8 + ((lane & 3) << 1) + j;
                    if (v > m) { m = v; id = c; }          // ascending -> first kept
                }
#pragma unroll
            for (int o = 1; o <= 2; o <<= 1) {
                float om = __shfl_xor_sync(0xffffffffu, m, o);
                int  oid = __shfl_xor_sync(0xffffffffu, id, o);
                if (om > m || (om == m && oid < id)) { m = om; id = oid; }
            }
            if ((lane & 3) == 0) {
                int r = wm + im * 16 + half * 8 + (lane >> 2);
                s_max[r * 4 + warpN] = m; s_idx[r * 4 + warpN] = id;
            }
        }
    __syncthreads();

    // phase 2: sumexp relative to the TILE-WIDE row max
#pragma unroll
    for (int im = 0; im < 2; im++)
#pragma unroll
        for (int half = 0; half < 2; half++) {
            int r = wm + im * 16 + half * 8 + (lane >> 2);
            float M = fmaxf(fmaxf(s_max[r * 4 + 0], s_max[r * 4 + 1]),
                            fmaxf(s_max[r * 4 + 2], s_max[r * 4 + 3]));
            float su = 0.f;
#pragma unroll
            for (int in = 0; in < 8; in++)
#pragma unroll
                for (int j = 0; j < 2; j++)
                    su += fex2((acc[im][in][half * 2 + j] - M) * EX2_SCALE);
#pragma unroll
            for (int o = 1; o <= 2; o <<= 1)
                su += __shfl_xor_sync(0xffffffffu, su, o);
            if ((lane & 3) == 0) s_sum[r * 4 + warpN] = su;
        }
    __syncthreads();

    // phase 3: combine 4 warp-columns (all already relative to tile max)
    if (tid < 128) {
        int r = tid;
        float M = s_max[r * 4 + 0]; int I = s_idx[r * 4 + 0];
#pragma unroll
        for (int c = 1; c < 4; c++) {
            float om = s_max[r * 4 + c]; int oid = s_idx[r * 4 + c];
            if (om > M || (om == M && oid < I)) { M = om; I = oid; }
        }
        float S = s_sum[r * 4 + 0] + s_sum[r * 4 + 1] + s_sum[r * 4 + 2] + s_sum[r * 4 + 3];
        size_t o = (size_t)(brow + r) * NTILE + blockIdx.x;
        g_pmax[o] = M; g_pidx[o] = I; g_psum[o] = S;
    }
}

// ---------------- kernel 3: merge 32 tile partials per row (1 warp/row) ----
__global__ __launch_bounds__(256) void merge_kernel() {
    int row  = blockIdx.x * 8 + (threadIdx.x >> 5);
    int lane = threadIdx.x & 31;
    size_t b = (size_t)row * NTILE;
    float m  = g_pmax[b + lane];
    int   id = g_pidx[b + lane];
    float su = g_psum[b + lane];
#pragma unroll
    for (int o = 1; o < 32; o <<= 1) {
        float om = __shfl_xor_sync(0xffffffffu, m, o);
        int  oid = __shfl_xor_sync(0xffffffffu, id, o);
        float os = __shfl_xor_sync(0xffffffffu, su, o);
        float M = fmaxf(m, om);
        float S = su * fexp((m - M) * INV_T) + os * fexp((om - M) * INV_T);
        int   I = (om > m || (om == m && oid < id)) ? oid : id;
        m = M; su = S; id = I;
    }
    if (lane == 0) {
        g_logl[row] = logf(su);      // -logp at argmax (positive logit == row max)
        g_pos[row]  = id;
    }
}

// ---------------- kernel 4: nn_sim[i] = <B[pos[i]], B[pos[i+1]]> -----------
__global__ __launch_bounds__(256) void nn_kernel() {
    int i = blockIdx.x * 8 + (threadIdx.x >> 5);
    if (i >= N_ROWS - 1) return;
    int lane = threadIdx.x & 31;
    const uint4* u = (const uint4*)(g_B + (size_t)g_pos[i]     * H_DIM);
    const uint4* v = (const uint4*)(g_B + (size_t)g_pos[i + 1] * H_DIM);
    float acc = 0.f;
#pragma unroll
    for (int k = 0; k < 4; k++) {
        uint4 a = u[lane + 32 * k];
        uint4 b = v[lane + 32 * k];
        const __nv_bfloat162* pa = (const __nv_bfloat162*)&a;
        const __nv_bfloat162* pb = (const __nv_bfloat162*)&b;
#pragma unroll
        for (int q = 0; q < 4; q++) {
            float2 fa = __bfloat1622float2(pa[q]);
            float2 fb = __bfloat1622float2(pb[q]);
            acc = fmaf(fa.x, fb.x, acc);
            acc = fmaf(fa.y, fb.y, acc);
        }
    }
#pragma unroll
    for (int o = 16; o; o >>= 1) acc += __shfl_xor_sync(0xffffffffu, acc, o);
    if (lane == 0) g_nn[i] = acc;
}

// ---------------- kernel 5: final deterministic reduction ------------------
__global__ __launch_bounds__(256) void final_kernel(float* __restrict__ out) {
    __shared__ float s1[256], s2[256];
    int t = threadIdx.x;
    float a = 0.f, b = 0.f;
    for (int j = t; j < N_ROWS; j += 256) a += g_logl[j];
    for (int j = t; j < N_ROWS - 1; j += 256) b += g_nn[j];
    s1[t] = a; s2[t] = b;
    __syncthreads();
    for (int s = 128; s > 0; s >>= 1) {
        if (t < s) { s1[t] += s1[t + s]; s2[t] += s2[t + s]; }
        __syncthreads();
    }
    if (t == 0) {
        out[0] = s1[0] / (float)N_ROWS;
        out[1] = 1.0f - s2[0] / (float)(N_ROWS - 1);
    }
}

// ---------------- launcher --------------------------------------------------
extern "C" void kernel_launch(void* const* d_in, const int* in_sizes, int n_in,
                              void* d_out, int out_size) {
    const float* h_source = (const float*)d_in[0];
    const float* h_target = (const float*)d_in[1];
    float* out = (float*)d_out;

    norm_kernel<<<2 * N_ROWS, 256>>>(h_source, h_target);

    cudaFuncSetAttribute(gemm_fused_kernel, cudaFuncAttributeMaxDynamicSharedMemorySize, SMEM_DYN);
    dim3 grid(N_ROWS / TN, N_ROWS / TM);   // 32 x 64
    gemm_fused_kernel<<<grid, NT, SMEM_DYN>>>();

    merge_kernel<<<N_ROWS / 8, 256>>>();
    nn_kernel<<<N_ROWS / 8, 256>>>();
    final_kernel<<<1, 256>>>(out);
}

// round 13
// speedup vs baseline: 1.1895x; 1.1895x over previous
#include <cuda_runtime.h>
#include <cuda.h>
#include <cuda_bf16.h>
#include <cstdint>
#include <math.h>

#define N_ROWS 8192
#define H_DIM  1024
#define NTILE  64                    // N_ROWS / 128 column tiles
#define INV_T  (1.0f/0.07f)
#define EX2_SCALE 20.609929f         // INV_T * log2(e)

// GEMM tiling: CTA 128x128, BK=64, 3 stages (TMA-filled), 8 warps 32x64, 2 CTAs/SM
#define TM 128
#define TN 128
#define KC 64
#define KT_STEPS (H_DIM / KC)        // 16
#define ST 3
#define A_BYTES (TM * 128)           // 16 KB
#define B_BYTES (TN * 128)           // 16 KB
#define STAGE_BYTES (A_BYTES + B_BYTES)      // 32 KB
#define SMEM_DYN (1024 + ST * STAGE_BYTES + 64)  // stages + mbarriers

// ---------------- scratch (device globals; no runtime allocation) ----------
__device__ __nv_bfloat16 g_A[(size_t)N_ROWS * H_DIM];
__device__ __nv_bfloat16 g_B[(size_t)N_ROWS * H_DIM];
__device__ float g_pmax[(size_t)N_ROWS * NTILE];
__device__ int   g_pidx[(size_t)N_ROWS * NTILE];
__device__ float g_psum[(size_t)N_ROWS * NTILE];   // relative to g_pmax
__device__ float g_logl[N_ROWS];
__device__ int   g_pos[N_ROWS];
__device__ float g_nn[N_ROWS];

// ---------------- helpers ---------------------------------------------------
__device__ __forceinline__ float fex2(float x) {
    float y; asm("ex2.approx.f32 %0, %1;" : "=f"(y) : "f"(x)); return y;
}
// exp(x) on FMA pipe for the merge kernel (x <= 0)
__device__ __forceinline__ float fexp(float x) {
    float t = x * 1.4426950408889634f;
    float fl = floorf(t);
    float f = t - fl;
    float p = 1.5403530e-4f;
    p = fmaf(p, f, 1.3333558e-3f);
    p = fmaf(p, f, 9.6181291e-3f);
    p = fmaf(p, f, 5.5504110e-2f);
    p = fmaf(p, f, 2.4022651e-1f);
    p = fmaf(p, f, 6.9314718e-1f);
    p = fmaf(p, f, 1.0f);
    return __int_as_float((uint32_t)((int)fl + 127) << 23) * p;
}
__device__ __forceinline__ uint32_t sw128(uint32_t off) {   // Swizzle<3,4,3>
    return off ^ ((off >> 3) & 0x70);
}
#define LDSM4(r0, r1, r2, r3, addr)                                            \
    asm volatile("ldmatrix.sync.aligned.m8n8.x4.shared.b16 {%0,%1,%2,%3}, [%4];" \
                 : "=r"(r0), "=r"(r1), "=r"(r2), "=r"(r3) : "r"(addr))
#define HMMA(acc, a, b)                                                        \
    asm volatile("mma.sync.aligned.m16n8k16.row.col.f32.bf16.bf16.f32 "        \
                 "{%0,%1,%2,%3},{%4,%5,%6,%7},{%8,%9},{%0,%1,%2,%3};"          \
                 : "+f"((acc)[0]), "+f"((acc)[1]), "+f"((acc)[2]), "+f"((acc)[3]) \
                 : "r"((a)[0]), "r"((a)[1]), "r"((a)[2]), "r"((a)[3]),         \
                   "r"((b)[0]), "r"((b)[1]))

#define MBARRIER_INIT(mb, c) \
    asm volatile("mbarrier.init.shared.b64 [%0], %1;" :: "r"((uint32_t)(mb)), "r"((uint32_t)(c)) : "memory")
#define MBARRIER_EXPECT_TX(mb, bytes) \
    asm volatile("mbarrier.arrive.expect_tx.shared.b64 _, [%0], %1;" \
                 :: "r"((uint32_t)(mb)), "r"((uint32_t)(bytes)) : "memory")
#define MBARRIER_WAIT_PARITY(mb, ph) do {                                          \
    uint32_t _mb = (uint32_t)(mb), _ph = (uint32_t)(ph), _done;                    \
    asm volatile("{\n\t.reg .pred p;\n\t"                                          \
        "mbarrier.try_wait.parity.acquire.cta.shared::cta.b64 p, [%1], %2;\n\t"    \
        "selp.b32 %0, 1, 0, p;\n\t}" : "=r"(_done) : "r"(_mb), "r"(_ph) : "memory"); \
    if (!_done) {                                                                  \
        asm volatile("{\n\t.reg .pred P1;\n\t"                                     \
            "WL_%=:\n\t"                                                           \
            "mbarrier.try_wait.parity.acquire.cta.shared::cta.b64 P1, [%0], %1, 0x989680;\n\t" \
            "@P1 bra.uni WD_%=;\n\t"                                               \
            "bra.uni WL_%=;\n\t"                                                   \
            "WD_%=:\n\t}" :: "r"(_mb), "r"(_ph) : "memory");                       \
    }                                                                              \
} while (0)
#define TMA_2D(smem, mapp, cx, cy, mb)                                             \
    asm volatile("cp.async.bulk.tensor.2d.shared::cta.global.tile.mbarrier::complete_tx::bytes " \
                 "[%0], [%1, {%2, %3}], [%4];"                                     \
                 :: "r"((uint32_t)(smem)), "l"(mapp), "r"((int)(cx)), "r"((int)(cy)), \
                    "r"((uint32_t)(mb)) : "memory")

// ---------------- kernel 1: row L2-normalize -> bf16 -----------------------
__global__ __launch_bounds__(256) void norm_kernel(const float* __restrict__ src,
                                                   const float* __restrict__ tgt) {
    int row = blockIdx.x;
    const float* in;
    __nv_bfloat16* out;
    if (row < N_ROWS) { in = src + (size_t)row * H_DIM;            out = g_A + (size_t)row * H_DIM; }
    else              { in = tgt + (size_t)(row - N_ROWS) * H_DIM; out = g_B + (size_t)(row - N_ROWS) * H_DIM; }

    int t = threadIdx.x;                          // cols 4t..4t+3
    float4 v = ((const float4*)in)[t];
    float ss = v.x * v.x + v.y * v.y + v.z * v.z + v.w * v.w;
#pragma unroll
    for (int o = 16; o; o >>= 1) ss += __shfl_xor_sync(0xffffffffu, ss, o);
    __shared__ float red[8];
    if ((t & 31) == 0) red[t >> 5] = ss;
    __syncthreads();
    float total = red[0] + red[1] + red[2] + red[3] + red[4] + red[5] + red[6] + red[7];
    float sc = 1.0f / fmaxf(sqrtf(total), 1e-12f);

    __nv_bfloat162 p0; p0.x = __float2bfloat16(v.x * sc); p0.y = __float2bfloat16(v.y * sc);
    __nv_bfloat162 p1; p1.x = __float2bfloat16(v.z * sc); p1.y = __float2bfloat16(v.w * sc);
    ((__nv_bfloat162*)out)[2 * t]     = p0;
    ((__nv_bfloat162*)out)[2 * t + 1] = p1;
}

// ---------------- kernel 2: HMMA GEMM (128x128, TMA loads) + fused softmax --
// 8 warps as 4(M) x 2(N), warp tile 32x64; 2 CTAs/SM.
// TMA fills each 32KB stage (A box 64x128 + B box 64x128 bf16, SW128),
// mbarrier expect_tx(32768) completes per stage; single __syncthreads per kt
// orders last iteration's LDSM reads before that stage is refilled.
__global__ __launch_bounds__(256, 2) void gemm_fused_kernel(
        const __grid_constant__ CUtensorMap tmA,
        const __grid_constant__ CUtensorMap tmB) {
    extern __shared__ __align__(16) char dsm[];
    uint32_t raw  = (uint32_t)__cvta_generic_to_shared(dsm);
    uint32_t base = (raw + 1023u) & ~1023u;
    uint32_t mbar = base + ST * STAGE_BYTES;       // full[s] at mbar + 8*s

    const int tid   = threadIdx.x;
    const int lane  = tid & 31;
    const int warp  = tid >> 5;
    const int warpM = warp & 3;             // 0..3 -> rows warpM*32
    const int warpN = warp >> 2;            // 0..1 -> cols warpN*64
    const int wm = warpM * 32;
    const int wn = warpN * 64;
    const int brow = blockIdx.y * TM;
    const int bcol = blockIdx.x * TN;

    float acc[2][8][4];
#pragma unroll
    for (int im = 0; im < 2; im++)
#pragma unroll
        for (int in = 0; in < 8; in++)
#pragma unroll
            for (int k = 0; k < 4; k++) acc[im][in][k] = 0.f;

    // swizzled ldmatrix bases; k-slice step kb hits bits 5-6 only:
    // sw128(o + kb) == sw128(o) ^ kb   (XOR — swizzle may set bits 5-6)
    uint32_t aoff[2], boff[4];
#pragma unroll
    for (int im = 0; im < 2; im++)
        aoff[im] = sw128((uint32_t)((wm + im * 16 + (lane & 15)) * 128 + ((lane >> 4) << 4)));
#pragma unroll
    for (int ib = 0; ib < 4; ib++)
        boff[ib] = sw128((uint32_t)((wn + ib * 16 + ((lane >> 4) << 3) + (lane & 7)) * 128
                                    + (((lane >> 3) & 1) << 4)));

    // init mbarriers, then prologue-issue stages 0..2 from one thread
    if (tid == 0) {
#pragma unroll
        for (int p = 0; p < ST; p++) MBARRIER_INIT(mbar + 8 * p, 1);
    }
    __syncthreads();
    if (tid == 0) {
#pragma unroll
        for (int p = 0; p < ST; p++) {
            uint32_t stg = base + p * STAGE_BYTES;
            MBARRIER_EXPECT_TX(mbar + 8 * p, STAGE_BYTES);
            TMA_2D(stg,           &tmA, p * KC, brow, mbar + 8 * p);
            TMA_2D(stg + A_BYTES, &tmB, p * KC, bcol, mbar + 8 * p);
        }
    }

    for (int j = 0; j < KT_STEPS; j++) {
        int s = j % ST;
        __syncthreads();    // all warps finished iter j-1's reads of stage (j-1)%3
        if (tid == 0 && j >= 1 && j + 2 < KT_STEPS) {
            int st = (j + 2) % ST;     // == (j-1)%3: freed by the barrier above
            uint32_t stg = base + st * STAGE_BYTES;
            MBARRIER_EXPECT_TX(mbar + 8 * st, STAGE_BYTES);
            TMA_2D(stg,           &tmA, (j + 2) * KC, brow, mbar + 8 * st);
            TMA_2D(stg + A_BYTES, &tmB, (j + 2) * KC, bcol, mbar + 8 * st);
        }
        MBARRIER_WAIT_PARITY(mbar + 8 * s, (j / ST) & 1);

        uint32_t aT = base + s * STAGE_BYTES;
        uint32_t bT = aT + A_BYTES;
#pragma unroll
        for (int ks = 0; ks < 4; ks++) {            // 4 x k16 slices
            uint32_t kb = (uint32_t)(ks * 32);
            uint32_t a[2][4], b[4][4];
#pragma unroll
            for (int im = 0; im < 2; im++)
                LDSM4(a[im][0], a[im][1], a[im][2], a[im][3], aT + (aoff[im] ^ kb));
#pragma unroll
            for (int ib = 0; ib < 4; ib++)
                LDSM4(b[ib][0], b[ib][1], b[ib][2], b[ib][3], bT + (boff[ib] ^ kb));
#pragma unroll
            for (int im = 0; im < 2; im++)
#pragma unroll
                for (int ib = 0; ib < 4; ib++) {
                    HMMA(acc[im][2 * ib],     a[im], &b[ib][0]);
                    HMMA(acc[im][2 * ib + 1], a[im], &b[ib][2]);
                }
        }
    }
    __syncthreads();        // all warps done with final stage before SMEM reuse

    // ---- epilogue: reuse stage SMEM for per-row partials (R11-proven) ----
    float* s_max = (float*)(dsm + (base - raw));          // [128][2]
    int*   s_idx = (int*)  (s_max + 128 * 2);
    float* s_sum = (float*)(s_idx + 128 * 2);

    // phase 1: per-warp (max, argmax) over its 64 cols
#pragma unroll
    for (int im = 0; im < 2; im++)
#pragma unroll
        for (int half = 0; half < 2; half++) {
            float m = -3.402823e38f; int id = 0;
#pragma unroll
            for (int in = 0; in < 8; in++)
#pragma unroll
                for (int j = 0; j < 2; j++) {
                    float v = acc[im][in][half * 2 + j];
                    int c = bcol + wn + in * 8 + ((lane & 3) << 1) + j;
                    if (v > m) { m = v; id = c; }          // ascending -> first kept
                }
#pragma unroll
            for (int o = 1; o <= 2; o <<= 1) {
                float om = __shfl_xor_sync(0xffffffffu, m, o);
                int  oid = __shfl_xor_sync(0xffffffffu, id, o);
                if (om > m || (om == m && oid < id)) { m = om; id = oid; }
            }
            if ((lane & 3) == 0) {
                int r = wm + im * 16 + half * 8 + (lane >> 2);
                s_max[r * 2 + warpN] = m; s_idx[r * 2 + warpN] = id;
            }
        }
    __syncthreads();

    // phase 2: sumexp relative to the TILE-WIDE row max
#pragma unroll
    for (int im = 0; im < 2; im++)
#pragma unroll
        for (int half = 0; half < 2; half++) {
            int r = wm + im * 16 + half * 8 + (lane >> 2);
            float M = fmaxf(s_max[r * 2 + 0], s_max[r * 2 + 1]);
            float su = 0.f;
#pragma unroll
            for (int in = 0; in < 8; in++)
#pragma unroll
                for (int j = 0; j < 2; j++)
                    su += fex2((acc[im][in][half * 2 + j] - M) * EX2_SCALE);
#pragma unroll
            for (int o = 1; o <= 2; o <<= 1)
                su += __shfl_xor_sync(0xffffffffu, su, o);
            if ((lane & 3) == 0) s_sum[r * 2 + warpN] = su;
        }
    __syncthreads();

    // phase 3: combine 2 warp-columns (both already relative to tile max)
    if (tid < 128) {
        int r = tid;
        float m0 = s_max[r * 2 + 0], m1 = s_max[r * 2 + 1];
        float M; int I;
        if (m1 > m0) { M = m1; I = s_idx[r * 2 + 1]; }
        else         { M = m0; I = s_idx[r * 2 + 0]; }
        float S = s_sum[r * 2 + 0] + s_sum[r * 2 + 1];
        size_t o = (size_t)(brow + r) * NTILE + blockIdx.x;
        g_pmax[o] = M; g_pidx[o] = I; g_psum[o] = S;
    }
}

// ---------------- kernel 3: merge 64 tile partials per row (1 warp/row) ----
__global__ __launch_bounds__(256) void merge_kernel() {
    int row  = blockIdx.x * 8 + (threadIdx.x >> 5);
    int lane = threadIdx.x & 31;
    size_t b = (size_t)row * NTILE;

    float m  = g_pmax[b + lane];
    int   id = g_pidx[b + lane];
    float su = g_psum[b + lane];
    {
        float om = g_pmax[b + lane + 32];
        int  oid = g_pidx[b + lane + 32];
        float os = g_psum[b + lane + 32];
        float M = fmaxf(m, om);
        float S = su * fexp((m - M) * INV_T) + os * fexp((om - M) * INV_T);
        int   I = (om > m || (om == m && oid < id)) ? oid : id;
        m = M; su = S; id = I;
    }
#pragma unroll
    for (int o = 1; o < 32; o <<= 1) {
        float om = __shfl_xor_sync(0xffffffffu, m, o);
        int  oid = __shfl_xor_sync(0xffffffffu, id, o);
        float os = __shfl_xor_sync(0xffffffffu, su, o);
        float M = fmaxf(m, om);
        float S = su * fexp((m - M) * INV_T) + os * fexp((om - M) * INV_T);
        int   I = (om > m || (om == m && oid < id)) ? oid : id;
        m = M; su = S; id = I;
    }
    if (lane == 0) {
        g_logl[row] = logf(su);      // -logp at argmax (positive logit == row max)
        g_pos[row]  = id;
    }
}

// ---------------- kernel 4: nn_sim[i] = <B[pos[i]], B[pos[i+1]]> -----------
__global__ __launch_bounds__(256) void nn_kernel() {
    int i = blockIdx.x * 8 + (threadIdx.x >> 5);
    if (i >= N_ROWS - 1) return;
    int lane = threadIdx.x & 31;
    const uint4* u = (const uint4*)(g_B + (size_t)g_pos[i]     * H_DIM);
    const uint4* v = (const uint4*)(g_B + (size_t)g_pos[i + 1] * H_DIM);
    float acc = 0.f;
#pragma unroll
    for (int k = 0; k < 4; k++) {
        uint4 a = u[lane + 32 * k];
        uint4 b = v[lane + 32 * k];
        const __nv_bfloat162* pa = (const __nv_bfloat162*)&a;
        const __nv_bfloat162* pb = (const __nv_bfloat162*)&b;
#pragma unroll
        for (int q = 0; q < 4; q++) {
            float2 fa = __bfloat1622float2(pa[q]);
            float2 fb = __bfloat1622float2(pb[q]);
            acc = fmaf(fa.x, fb.x, acc);
            acc = fmaf(fa.y, fb.y, acc);
        }
    }
#pragma unroll
    for (int o = 16; o; o >>= 1) acc += __shfl_xor_sync(0xffffffffu, acc, o);
    if (lane == 0) g_nn[i] = acc;
}

// ---------------- kernel 5: final deterministic reduction ------------------
__global__ __launch_bounds__(256) void final_kernel(float* __restrict__ out) {
    __shared__ float s1[256], s2[256];
    int t = threadIdx.x;
    float a = 0.f, b = 0.f;
    for (int j = t; j < N_ROWS; j += 256) a += g_logl[j];
    for (int j = t; j < N_ROWS - 1; j += 256) b += g_nn[j];
    s1[t] = a; s2[t] = b;
    __syncthreads();
    for (int s = 128; s > 0; s >>= 1) {
        if (t < s) { s1[t] += s1[t + s]; s2[t] += s2[t + s]; }
        __syncthreads();
    }
    if (t == 0) {
        out[0] = s1[0] / (float)N_ROWS;
        out[1] = 1.0f - s2[0] / (float)(N_ROWS - 1);
    }
}

// ---------------- host: tensormap encode (runtime-API entry point) ---------
typedef CUresult (*EncodeTiledFn)(
    CUtensorMap*, CUtensorMapDataType, cuuint32_t, void*,
    const cuuint64_t*, const cuuint64_t*, const cuuint32_t*, const cuuint32_t*,
    CUtensorMapInterleave, CUtensorMapSwizzle, CUtensorMapL2promotion,
    CUtensorMapFloatOOBfill);

static void encode_map(EncodeTiledFn enc, CUtensorMap* m, void* ptr) {
    cuuint64_t dims[2]    = {(cuuint64_t)H_DIM, (cuuint64_t)N_ROWS};
    cuuint64_t strides[1] = {(cuuint64_t)H_DIM * 2};      // bytes per row
    cuuint32_t box[2]     = {KC, TM};                     // 64 bf16 (128B) x 128 rows
    cuuint32_t estr[2]    = {1, 1};
    enc(m, CU_TENSOR_MAP_DATA_TYPE_BFLOAT16, 2, ptr, dims, strides, box, estr,
        CU_TENSOR_MAP_INTERLEAVE_NONE, CU_TENSOR_MAP_SWIZZLE_128B,
        CU_TENSOR_MAP_L2_PROMOTION_L2_128B, CU_TENSOR_MAP_FLOAT_OOB_FILL_NONE);
}

// ---------------- launcher --------------------------------------------------
extern "C" void kernel_launch(void* const* d_in, const int* in_sizes, int n_in,
                              void* d_out, int out_size) {
    const float* h_source = (const float*)d_in[0];
    const float* h_target = (const float*)d_in[1];
    float* out = (float*)d_out;

    // resolve cuTensorMapEncodeTiled through the runtime (no -lcuda needed)
    EncodeTiledFn enc = nullptr;
    {
        void* fn = nullptr;
        cudaDriverEntryPointQueryResult st;
#if CUDART_VERSION >= 12050
        cudaGetDriverEntryPointByVersion("cuTensorMapEncodeTiled", &fn, 12000,
                                         cudaEnableDefault, &st);
#else
        cudaGetDriverEntryPoint("cuTensorMapEncodeTiled", &fn,
                                cudaEnableDefault, &st);
#endif
        enc = (EncodeTiledFn)fn;
    }
    void *pA = nullptr, *pB = nullptr;
    cudaGetSymbolAddress(&pA, g_A);
    cudaGetSymbolAddress(&pB, g_B);
    CUtensorMap tmA, tmB;
    encode_map(enc, &tmA, pA);
    encode_map(enc, &tmB, pB);

    norm_kernel<<<2 * N_ROWS, 256>>>(h_source, h_target);

    cudaFuncSetAttribute(gemm_fused_kernel, cudaFuncAttributeMaxDynamicSharedMemorySize, SMEM_DYN);
    dim3 grid(N_ROWS / TN, N_ROWS / TM);   // 64 x 64
    gemm_fused_kernel<<<grid, 256, SMEM_DYN>>>(tmA, tmB);

    merge_kernel<<<N_ROWS / 8, 256>>>();
    nn_kernel<<<N_ROWS / 8, 256>>>();
    final_kernel<<<1, 256>>>(out);
}